// round 1
// baseline (speedup 1.0000x reference)
#include <cuda_runtime.h>
#include <math.h>
#include <stdint.h>

#define MAXB 64
#define MAXP 8732
#define MAXO 16
#define WPB 8   // warps per block in loss kernel
#define NPARTX ((MAXP + WPB - 1) / WPB)   // 1092
#define MAXPART (NPARTX * MAXB)           // 69888

// ---- scratch (static __device__; no runtime allocation) ----
__device__ float g_best_ov[MAXB * MAXP];
__device__ int   g_best_idx[MAXB * MAXP];
__device__ float g_mined[MAXB * MAXP];
__device__ int   g_num_pos[MAXB];
__device__ float g_negsum[MAXB];
__device__ float g_part_l[MAXPART];
__device__ float g_part_c[MAXPART];

// ---------------------------------------------------------------------------
__global__ void zero_kernel(int B) {
    int i = threadIdx.x;
    if (i < B) g_num_pos[i] = 0;
}

// ---------------------------------------------------------------------------
// Per-batch matching: per-prior best truth (max over O), per-truth best prior
// (argmax over P, first-index on tie), then torch-style overrides.
__global__ void match_kernel(const float* __restrict__ priors,
                             const float* __restrict__ targets,
                             int P, int O) {
    int b = blockIdx.x;
    __shared__ float sh_t[MAXO * 5];
    __shared__ unsigned long long sh_key[MAXO];
    int tid = threadIdx.x;

    if (tid < O * 5) sh_t[tid] = targets[b * O * 5 + tid];
    if (tid < O)     sh_key[tid] = 0ull;
    __syncthreads();

    unsigned long long lkey[MAXO];
#pragma unroll
    for (int o = 0; o < MAXO; o++) lkey[o] = 0ull;

    float* bov = g_best_ov + (size_t)b * P;
    int*   bix = g_best_idx + (size_t)b * P;

    for (int p = tid; p < P; p += blockDim.x) {
        float cx = priors[p * 4 + 0], cy = priors[p * 4 + 1];
        float pw = priors[p * 4 + 2], ph = priors[p * 4 + 3];
        float px0 = cx - pw * 0.5f, py0 = cy - ph * 0.5f;
        float px1 = cx + pw * 0.5f, py1 = cy + ph * 0.5f;
        float areaP = pw * ph;
        float bestv = -1.0f; int besti = 0;
        for (int o = 0; o < O; o++) {
            float t0 = sh_t[o * 5 + 0], t1 = sh_t[o * 5 + 1];
            float t2 = sh_t[o * 5 + 2], t3 = sh_t[o * 5 + 3];
            float ltx = fmaxf(t0, px0), lty = fmaxf(t1, py0);
            float rbx = fminf(t2, px1), rby = fminf(t3, py1);
            float iw = fmaxf(rbx - ltx, 0.f), ih = fmaxf(rby - lty, 0.f);
            float inter = iw * ih;
            float areaT = (t2 - t0) * (t3 - t1);
            float ov = inter / (areaT + areaP - inter);
            if (ov > bestv) { bestv = ov; besti = o; }   // strict > : first index wins
            unsigned long long key =
                ((unsigned long long)__float_as_uint(ov) << 32) |
                (unsigned long long)(0xFFFFFFFFu - (unsigned)p);  // tie -> min p
            if (key > lkey[o]) lkey[o] = key;
        }
        bov[p] = bestv;
        bix[p] = besti;
    }
    for (int o = 0; o < O; o++) atomicMax(&sh_key[o], lkey[o]);
    __syncthreads();
    if (tid == 0) {
        // sequential, last truth wins on duplicate best priors (torch semantics)
        for (int o = 0; o < O; o++) {
            unsigned p = 0xFFFFFFFFu - (unsigned)(sh_key[o] & 0xFFFFFFFFu);
            bov[p] = 2.0f;
            bix[p] = o;
        }
    }
}

// ---------------------------------------------------------------------------
// Warp-per-prior: conf logsumexp + gather, smooth-L1 loc loss on positives,
// mined value store, per-block deterministic partials.
__global__ void loss_kernel(const float* __restrict__ loc_data,
                            const float* __restrict__ conf_data,
                            const float* __restrict__ priors,
                            const float* __restrict__ targets,
                            int P, int C, int O) {
    int b = blockIdx.y;
    int warp = threadIdx.x >> 5;
    int lane = threadIdx.x & 31;
    int p = blockIdx.x * WPB + warp;

    float ll = 0.f, cpos = 0.f;
    int np = 0;

    if (p < P) {
        size_t bp = (size_t)b * P + p;
        float ov = g_best_ov[bp];
        int ti = g_best_idx[bp];
        const float* t = targets + ((size_t)b * O + ti) * 5;
        int conf_t = 0;
        if (ov >= 0.5f) conf_t = (int)t[4] + 1;
        bool pos = (conf_t > 0);

        float x = (lane < C) ? conf_data[bp * C + lane] : -INFINITY;
        float m = x;
#pragma unroll
        for (int off = 16; off; off >>= 1)
            m = fmaxf(m, __shfl_xor_sync(0xFFFFFFFFu, m, off));
        float e = (lane < C) ? expf(x - m) : 0.f;
#pragma unroll
        for (int off = 16; off; off >>= 1)
            e += __shfl_xor_sync(0xFFFFFFFFu, e, off);
        float lse = m + logf(e);
        float gathered = __shfl_sync(0xFFFFFFFFu, x, conf_t);
        float lc = lse - gathered;

        if (lane == 0) {
            g_mined[bp] = pos ? 0.f : lc;
            if (pos) {
                cpos = lc;
                np = 1;
                float cx = priors[p * 4 + 0], cy = priors[p * 4 + 1];
                float pw = priors[p * 4 + 2], ph = priors[p * 4 + 3];
                float mx0 = t[0], my0 = t[1], mx1 = t[2], my1 = t[3];
                float g0 = ((mx0 + mx1) * 0.5f - cx) / (0.1f * pw);
                float g1 = ((my0 + my1) * 0.5f - cy) / (0.1f * ph);
                float g2 = logf(fmaxf((mx1 - mx0) / pw, 1e-8f)) / 0.2f;
                float g3 = logf(fmaxf((my1 - my0) / ph, 1e-8f)) / 0.2f;
                const float* L = loc_data + bp * 4;
                float g4[4] = {g0, g1, g2, g3};
#pragma unroll
                for (int i = 0; i < 4; i++) {
                    float d = L[i] - g4[i];
                    float ad = fabsf(d);
                    ll += (ad < 1.f) ? 0.5f * d * d : ad - 0.5f;
                }
            }
        }
    }

    __shared__ float s_ll[WPB], s_cp[WPB];
    __shared__ int s_np[WPB];
    if (lane == 0) { s_ll[warp] = ll; s_cp[warp] = cpos; s_np[warp] = np; }
    __syncthreads();
    if (threadIdx.x == 0) {
        float tl = 0.f, tc = 0.f; int tn = 0;
        for (int w = 0; w < WPB; w++) { tl += s_ll[w]; tc += s_cp[w]; tn += s_np[w]; }
        int part = b * gridDim.x + blockIdx.x;
        g_part_l[part] = tl;
        g_part_c[part] = tc;
        if (tn) atomicAdd(&g_num_pos[b], tn);
    }
}

// ---------------------------------------------------------------------------
// Per-batch radix-select of top-k mined conf losses (k = min(3*np, P-np)),
// exact under ties, deterministic sums.
__global__ void mine_kernel(int P) {
    int b = blockIdx.x;
    const float* mv = g_mined + (size_t)b * P;
    int np = g_num_pos[b];
    int k = min(3 * np, P - np);

    __shared__ int hist[256];
    __shared__ unsigned s_prefix;
    __shared__ int s_kk;
    __shared__ float s_sum[256];

    if (k <= 0) {
        if (threadIdx.x == 0) g_negsum[b] = 0.f;
        return;
    }

    unsigned prefix = 0, pmask = 0;
    int kk = k;
    for (int shift = 24; shift >= 0; shift -= 8) {
        for (int i = threadIdx.x; i < 256; i += blockDim.x) hist[i] = 0;
        __syncthreads();
        for (int p = threadIdx.x; p < P; p += blockDim.x) {
            unsigned key = __float_as_uint(mv[p]);   // all values >= 0: bits order-preserving
            if ((key & pmask) == prefix)
                atomicAdd(&hist[(key >> shift) & 0xFF], 1);
        }
        __syncthreads();
        if (threadIdx.x == 0) {
            int cum = 0, bin = 255;
            for (; bin >= 0; bin--) {
                cum += hist[bin];
                if (cum >= kk) break;
            }
            if (bin < 0) bin = 0;  // safety (shouldn't happen)
            s_prefix = prefix | ((unsigned)bin << shift);
            s_kk = kk - (cum - hist[bin]);
        }
        __syncthreads();
        prefix = s_prefix;
        kk = s_kk;
        pmask |= 0xFFu << shift;
        __syncthreads();
    }

    float kth = __uint_as_float(prefix);
    float lsum = 0.f;
    for (int p = threadIdx.x; p < P; p += blockDim.x) {
        float v = mv[p];
        if (__float_as_uint(v) > prefix) lsum += v;
    }
    s_sum[threadIdx.x] = lsum;
    __syncthreads();
    if (threadIdx.x == 0) {
        float tot = 0.f;
        for (int i = 0; i < 256; i++) tot += s_sum[i];
        g_negsum[b] = tot + (float)kk * kth;
    }
}

// ---------------------------------------------------------------------------
__global__ void finalize_kernel(float* __restrict__ out, int nPart, int B) {
    __shared__ float s[256];
    int tid = threadIdx.x;

    float a = 0.f;
    for (int i = tid; i < nPart; i += 256) a += g_part_l[i];
    s[tid] = a;
    __syncthreads();
    __shared__ float sh_ll, sh_lc;
    if (tid == 0) {
        float t = 0.f;
        for (int i = 0; i < 256; i++) t += s[i];
        sh_ll = t;
    }
    __syncthreads();

    a = 0.f;
    for (int i = tid; i < nPart; i += 256) a += g_part_c[i];
    s[tid] = a;
    __syncthreads();
    if (tid == 0) {
        float t = 0.f;
        for (int i = 0; i < 256; i++) t += s[i];
        sh_lc = t;
        float loss_c = sh_lc;
        int N = 0;
        for (int bb = 0; bb < B; bb++) {
            loss_c += g_negsum[bb];
            N += g_num_pos[bb];
        }
        float fN = (float)N;
        out[0] = sh_ll / fN;
        out[1] = loss_c / fN;
    }
}

// ---------------------------------------------------------------------------
extern "C" void kernel_launch(void* const* d_in, const int* in_sizes, int n_in,
                              void* d_out, int out_size) {
    const float* loc     = (const float*)d_in[0];
    const float* conf    = (const float*)d_in[1];
    const float* priors  = (const float*)d_in[2];
    const float* targets = (const float*)d_in[3];

    int P = in_sizes[2] / 4;
    int B = in_sizes[0] / (P * 4);
    int C = in_sizes[1] / (B * P);
    int O = in_sizes[3] / (B * 5);
    float* out = (float*)d_out;

    zero_kernel<<<1, 256>>>(B);
    match_kernel<<<B, 256>>>(priors, targets, P, O);

    dim3 gridB((P + WPB - 1) / WPB, B);
    loss_kernel<<<gridB, WPB * 32>>>(loc, conf, priors, targets, P, C, O);

    mine_kernel<<<B, 256>>>(P);
    finalize_kernel<<<1, 256>>>(out, gridB.x * B, B);
}

// round 3
// speedup vs baseline: 1.1990x; 1.1990x over previous
#include <cuda_runtime.h>
#include <math.h>
#include <stdint.h>

#define MAXB 64
#define MAXP 8732
#define MAXO 16
#define WPB 8                              // warps per block in loss kernel
#define ACC_SCALE 67108864.0               // 2^26 fixed-point for deterministic atomics

// ---- scratch (static __device__; no runtime allocation) ----
__device__ float              g_best_ov[MAXB * MAXP];
__device__ int                g_best_idx[MAXB * MAXP];
__device__ float              g_mined[MAXB * MAXP];
__device__ int                g_num_pos[MAXB];
__device__ float              g_negsum[MAXB];
__device__ unsigned long long g_acc_l[MAXB];
__device__ unsigned long long g_acc_c[MAXB];
__device__ unsigned int       g_done;

// ---------------------------------------------------------------------------
// Per-batch matching, specialized for compile-time O (keeps lkey in registers).
template <int OO>
__global__ void __launch_bounds__(512, 2)
match_kernel_t(const float* __restrict__ priors,
               const float* __restrict__ targets,
               int P) {
    int b = blockIdx.x;
    __shared__ float sh_t[OO * 5];
    __shared__ unsigned long long sh_key[OO];
    int tid = threadIdx.x;

    if (tid == 0) {
        g_num_pos[b] = 0;
        g_acc_l[b] = 0ull;
        g_acc_c[b] = 0ull;
        if (b == 0) g_done = 0u;
    }
    if (tid < OO * 5) sh_t[tid] = targets[b * OO * 5 + tid];
    if (tid < OO)     sh_key[tid] = 0ull;
    __syncthreads();

    unsigned long long lkey[OO];
#pragma unroll
    for (int o = 0; o < OO; o++) lkey[o] = 0ull;

    float* bov = g_best_ov + (size_t)b * P;
    int*   bix = g_best_idx + (size_t)b * P;
    const float4* pr4 = (const float4*)priors;

    for (int p = tid; p < P; p += blockDim.x) {
        float4 pr = pr4[p];
        float px0 = pr.x - pr.z * 0.5f, py0 = pr.y - pr.w * 0.5f;
        float px1 = pr.x + pr.z * 0.5f, py1 = pr.y + pr.w * 0.5f;
        float areaP = pr.z * pr.w;
        float bestv = -1.0f; int besti = 0;
#pragma unroll
        for (int o = 0; o < OO; o++) {
            float t0 = sh_t[o * 5 + 0], t1 = sh_t[o * 5 + 1];
            float t2 = sh_t[o * 5 + 2], t3 = sh_t[o * 5 + 3];
            float ltx = fmaxf(t0, px0), lty = fmaxf(t1, py0);
            float rbx = fminf(t2, px1), rby = fminf(t3, py1);
            float iw = fmaxf(rbx - ltx, 0.f), ih = fmaxf(rby - lty, 0.f);
            float inter = iw * ih;
            float areaT = (t2 - t0) * (t3 - t1);
            float ov = inter / (areaT + areaP - inter);
            if (ov > bestv) { bestv = ov; besti = o; }   // strict > : first index wins
            unsigned long long key =
                ((unsigned long long)__float_as_uint(ov) << 32) |
                (unsigned long long)(0xFFFFFFFFu - (unsigned)p);  // tie -> min p
            if (key > lkey[o]) lkey[o] = key;
        }
        bov[p] = bestv;
        bix[p] = besti;
    }
#pragma unroll
    for (int o = 0; o < OO; o++) atomicMax(&sh_key[o], lkey[o]);
    __syncthreads();
    if (tid == 0) {
        // sequential; last truth wins on duplicate best priors (torch semantics)
        for (int o = 0; o < OO; o++) {
            unsigned p = 0xFFFFFFFFu - (unsigned)(sh_key[o] & 0xFFFFFFFFu);
            bov[p] = 2.0f;
            bix[p] = o;
        }
    }
}

// Generic fallback (O != 8): shared-atomic keys per truth.
__global__ void __launch_bounds__(512, 2)
match_kernel_gen(const float* __restrict__ priors,
                 const float* __restrict__ targets,
                 int P, int O) {
    int b = blockIdx.x;
    __shared__ float sh_t[MAXO * 5];
    __shared__ unsigned long long sh_key[MAXO];
    int tid = threadIdx.x;

    if (tid == 0) {
        g_num_pos[b] = 0;
        g_acc_l[b] = 0ull;
        g_acc_c[b] = 0ull;
        if (b == 0) g_done = 0u;
    }
    if (tid < O * 5) sh_t[tid] = targets[b * O * 5 + tid];
    if (tid < O)     sh_key[tid] = 0ull;
    __syncthreads();

    float* bov = g_best_ov + (size_t)b * P;
    int*   bix = g_best_idx + (size_t)b * P;
    const float4* pr4 = (const float4*)priors;

    for (int p = tid; p < P; p += blockDim.x) {
        float4 pr = pr4[p];
        float px0 = pr.x - pr.z * 0.5f, py0 = pr.y - pr.w * 0.5f;
        float px1 = pr.x + pr.z * 0.5f, py1 = pr.y + pr.w * 0.5f;
        float areaP = pr.z * pr.w;
        float bestv = -1.0f; int besti = 0;
        for (int o = 0; o < O; o++) {
            float t0 = sh_t[o * 5 + 0], t1 = sh_t[o * 5 + 1];
            float t2 = sh_t[o * 5 + 2], t3 = sh_t[o * 5 + 3];
            float ltx = fmaxf(t0, px0), lty = fmaxf(t1, py0);
            float rbx = fminf(t2, px1), rby = fminf(t3, py1);
            float iw = fmaxf(rbx - ltx, 0.f), ih = fmaxf(rby - lty, 0.f);
            float inter = iw * ih;
            float areaT = (t2 - t0) * (t3 - t1);
            float ov = inter / (areaT + areaP - inter);
            if (ov > bestv) { bestv = ov; besti = o; }
            unsigned long long key =
                ((unsigned long long)__float_as_uint(ov) << 32) |
                (unsigned long long)(0xFFFFFFFFu - (unsigned)p);
            atomicMax(&sh_key[o], key);
        }
        bov[p] = bestv;
        bix[p] = besti;
    }
    __syncthreads();
    if (tid == 0) {
        for (int o = 0; o < O; o++) {
            unsigned p = 0xFFFFFFFFu - (unsigned)(sh_key[o] & 0xFFFFFFFFu);
            bov[p] = 2.0f;
            bix[p] = o;
        }
    }
}

// ---------------------------------------------------------------------------
// Warp-per-prior: conf logsumexp + gather, smooth-L1 loc loss on positives,
// mined value store, per-batch fixed-point accumulators (deterministic).
__global__ void __launch_bounds__(WPB * 32)
loss_kernel(const float* __restrict__ loc_data,
            const float* __restrict__ conf_data,
            const float* __restrict__ priors,
            const float* __restrict__ targets,
            int P, int C, int O) {
    int b = blockIdx.y;
    int warp = threadIdx.x >> 5;
    int lane = threadIdx.x & 31;
    int p = blockIdx.x * WPB + warp;

    float ll = 0.f, cpos = 0.f;
    int np = 0;

    if (p < P) {
        size_t bp = (size_t)b * P + p;
        float ov = g_best_ov[bp];
        int ti = g_best_idx[bp];
        const float* t = targets + ((size_t)b * O + ti) * 5;
        int conf_t = 0;
        if (ov >= 0.5f) conf_t = (int)t[4] + 1;
        bool pos = (conf_t > 0);

        float x = (lane < C) ? conf_data[bp * C + lane] : -INFINITY;
        float m = x;
#pragma unroll
        for (int off = 16; off; off >>= 1)
            m = fmaxf(m, __shfl_xor_sync(0xFFFFFFFFu, m, off));
        float e = (lane < C) ? expf(x - m) : 0.f;
#pragma unroll
        for (int off = 16; off; off >>= 1)
            e += __shfl_xor_sync(0xFFFFFFFFu, e, off);
        float lse = m + logf(e);
        float gathered = __shfl_sync(0xFFFFFFFFu, x, conf_t);
        float lc = lse - gathered;

        if (lane == 0) {
            g_mined[bp] = pos ? 0.f : lc;
            if (pos) {
                cpos = lc;
                np = 1;
                float4 pr = ((const float4*)priors)[p];
                float mx0 = t[0], my0 = t[1], mx1 = t[2], my1 = t[3];
                float g0 = ((mx0 + mx1) * 0.5f - pr.x) / (0.1f * pr.z);
                float g1 = ((my0 + my1) * 0.5f - pr.y) / (0.1f * pr.w);
                float g2 = logf(fmaxf((mx1 - mx0) / pr.z, 1e-8f)) / 0.2f;
                float g3 = logf(fmaxf((my1 - my0) / pr.w, 1e-8f)) / 0.2f;
                float4 L = ((const float4*)loc_data)[bp];
                float Ld[4] = {L.x, L.y, L.z, L.w};
                float g4[4] = {g0, g1, g2, g3};
#pragma unroll
                for (int i = 0; i < 4; i++) {
                    float d = Ld[i] - g4[i];
                    float ad = fabsf(d);
                    ll += (ad < 1.f) ? 0.5f * d * d : ad - 0.5f;
                }
            }
        }
    }

    __shared__ float s_ll[WPB], s_cp[WPB];
    __shared__ int s_np[WPB];
    if (lane == 0) { s_ll[warp] = ll; s_cp[warp] = cpos; s_np[warp] = np; }
    __syncthreads();
    if (threadIdx.x == 0) {
        float tl = 0.f, tc = 0.f; int tn = 0;
        for (int w = 0; w < WPB; w++) { tl += s_ll[w]; tc += s_cp[w]; tn += s_np[w]; }
        if (tl != 0.f)
            atomicAdd(&g_acc_l[b], (unsigned long long)(long long)llrint((double)tl * ACC_SCALE));
        if (tc != 0.f)
            atomicAdd(&g_acc_c[b], (unsigned long long)(long long)llrint((double)tc * ACC_SCALE));
        if (tn) atomicAdd(&g_num_pos[b], tn);
    }
}

// ---------------------------------------------------------------------------
// Per-batch radix-select of top-k mined conf losses (k = min(3*np, P-np)),
// data staged in SMEM, exact under ties, deterministic. Last block finalizes.
__global__ void __launch_bounds__(512, 1)
mine_kernel(float* __restrict__ out, int P, int B) {
    int b = blockIdx.x;
    int tid = threadIdx.x;

    __shared__ unsigned sv[MAXP];      // 34928 B
    __shared__ int hist[256];
    __shared__ unsigned s_prefix;
    __shared__ int s_kk;
    __shared__ float s_red[16];
    __shared__ int s_last;

    const float* mv = g_mined + (size_t)b * P;
    for (int p = tid; p < P; p += blockDim.x)
        sv[p] = __float_as_uint(mv[p]);          // all >= 0: bits order-preserving

    int np = g_num_pos[b];
    int k = min(3 * np, P - np);
    float negsum = 0.f;

    if (k > 0) {
        unsigned prefix = 0, pmask = 0;
        int kk = k;
        for (int shift = 24; shift >= 0; shift -= 8) {
            if (tid < 256) hist[tid] = 0;
            __syncthreads();
            for (int p = tid; p < P; p += blockDim.x) {
                unsigned key = sv[p];
                if ((key & pmask) == prefix)
                    atomicAdd(&hist[(key >> shift) & 0xFF], 1);
            }
            __syncthreads();
            if (tid == 0) {
                int cum = 0, bin = 255;
                for (; bin >= 0; bin--) {
                    cum += hist[bin];
                    if (cum >= kk) break;
                }
                if (bin < 0) bin = 0;
                s_prefix = prefix | ((unsigned)bin << shift);
                s_kk = kk - (cum - hist[bin]);
            }
            __syncthreads();
            prefix = s_prefix;
            kk = s_kk;
            pmask |= 0xFFu << shift;
            __syncthreads();
        }

        float lsum = 0.f;
        for (int p = tid; p < P; p += blockDim.x) {
            unsigned key = sv[p];
            if (key > prefix) lsum += __uint_as_float(key);
        }
#pragma unroll
        for (int off = 16; off; off >>= 1)
            lsum += __shfl_xor_sync(0xFFFFFFFFu, lsum, off);
        if ((tid & 31) == 0) s_red[tid >> 5] = lsum;
        __syncthreads();
        if (tid == 0) {
            float tot = 0.f;
            int nw = blockDim.x >> 5;
            for (int i = 0; i < nw; i++) tot += s_red[i];
            negsum = tot + (float)kk * __uint_as_float(prefix);
        }
    }
    if (tid == 0) {
        g_negsum[b] = negsum;
        __threadfence();
        unsigned done = atomicAdd(&g_done, 1u);
        s_last = (done == (unsigned)(B - 1)) ? 1 : 0;
    }
    __syncthreads();
    if (s_last && tid == 0) {
        double ll = 0.0, lc = 0.0;
        int N = 0;
        for (int bb = 0; bb < B; bb++) {
            ll += (double)(long long)g_acc_l[bb];
            lc += (double)(long long)g_acc_c[bb];
            lc += (double)g_negsum[bb] * ACC_SCALE;
            N += g_num_pos[bb];
        }
        double fN = (double)N * ACC_SCALE;
        out[0] = (float)(ll / fN);
        out[1] = (float)(lc / fN);
    }
}

// ---------------------------------------------------------------------------
extern "C" void kernel_launch(void* const* d_in, const int* in_sizes, int n_in,
                              void* d_out, int out_size) {
    const float* loc     = (const float*)d_in[0];
    const float* conf    = (const float*)d_in[1];
    const float* priors  = (const float*)d_in[2];
    const float* targets = (const float*)d_in[3];

    int P = in_sizes[2] / 4;
    int B = in_sizes[0] / (P * 4);
    int C = in_sizes[1] / (B * P);
    int O = in_sizes[3] / (B * 5);
    float* out = (float*)d_out;

    if (O == 8)
        match_kernel_t<8><<<B, 512>>>(priors, targets, P);
    else
        match_kernel_gen<<<B, 512>>>(priors, targets, P, O);

    dim3 gridB((P + WPB - 1) / WPB, B);
    loss_kernel<<<gridB, WPB * 32>>>(loc, conf, priors, targets, P, C, O);

    mine_kernel<<<B, 512>>>(out, P, B);
}